// round 8
// baseline (speedup 1.0000x reference)
#include <cuda_runtime.h>
#include <cstdint>

#define BB 2
#define N1 4096
#define N2 8192
#define NSPLIT 8
#define KSEL 16

// ---------------- scratch (__device__ globals: allowed) ----------------
__device__ __align__(16) float g_f1n [BB*N1*64];
__device__ __align__(16) float g_f2n [BB*N2*64];
__device__ __align__(16) float g_p2r [BB*N2*64];
__device__ __align__(16) float g_p2ro[BB*N2*64];
__device__ __align__(16) float g_p2z [BB*N2*64];
__device__ __align__(16) float g_gp1r[BB*N1*64];
__device__ __align__(16) float g_gp1z[BB*N1*64];
__device__ __align__(16) float g_p1o [BB*N1*64];
__device__ float g_cosv[BB*N1*NSPLIT*8];
__device__ int   g_cosi[BB*N1*NSPLIT*8];
__device__ float g_eucv[BB*N1*NSPLIT*8];
__device__ int   g_euci[BB*N1*NSPLIT*8];
__device__ int   g_idx [BB*N1*KSEL];

// ---------------- helpers ----------------
__device__ __forceinline__ void fma2(unsigned long long& d, unsigned long long a, unsigned long long b) {
    asm("fma.rn.f32x2 %0, %1, %2, %0;" : "+l"(d) : "l"(a), "l"(b));
}
__device__ __forceinline__ float hsum2(unsigned long long v) {
    return __uint_as_float((unsigned)v) + __uint_as_float((unsigned)(v >> 32));
}
__device__ __forceinline__ float leaky(float x) { return fmaxf(x, 0.1f * x); }
__device__ __forceinline__ float sigm(float x) { return 1.f / (1.f + __expf(-x)); }

__device__ __forceinline__ void top8_insert(float (&tv)[8], int (&ti)[8], float v, int j) {
    #pragma unroll
    for (int t = 0; t < 8; t++) {
        if (v > tv[t]) { float fv = tv[t]; int fj = ti[t]; tv[t] = v; ti[t] = j; v = fv; j = fj; }
    }
}

// load one 64-float weight row (68-float padded) from smem into registers
__device__ __forceinline__ void loadrow(const float* __restrict__ W, int o, ulonglong2 (&w)[16]) {
    const ulonglong2* p = (const ulonglong2*)(W + o * 68);
    #pragma unroll
    for (int i = 0; i < 16; i++) w[i] = p[i];
}
// dot of register weight row with a 64-float smem vector (broadcast reads)
__device__ __forceinline__ float dotv64(const ulonglong2 (&w)[16], const float* __restrict__ v) {
    const ulonglong2* v2 = (const ulonglong2*)v;
    unsigned long long a0 = 0ull, a1 = 0ull, a2 = 0ull, a3 = 0ull;
    #pragma unroll
    for (int i = 0; i < 16; i += 2) {
        ulonglong2 x = v2[i];
        fma2(a0, w[i].x, x.x); fma2(a1, w[i].y, x.y);
        ulonglong2 y = v2[i + 1];
        fma2(a2, w[i + 1].x, y.x); fma2(a3, w[i + 1].y, y.y);
    }
    return (hsum2(a0) + hsum2(a1)) + (hsum2(a2) + hsum2(a3));
}

// ---------------- normalize: dst[b][n][c] = src[b][c][n] * rsqrt(sumsq+1e-8) ----------------
__global__ void k_normalize(const float* __restrict__ src_, float* __restrict__ dst_, int N) {
    __shared__ float s[64 * 65];
    __shared__ float inv[64];
    int b = blockIdx.y;
    int n0 = blockIdx.x * 64;
    const float* src = src_ + (size_t)b * 64 * N;
    for (int i = threadIdx.x; i < 4096; i += 256) {
        int c = i >> 6, n = i & 63;
        s[c * 65 + n] = src[(size_t)c * N + n0 + n];
    }
    __syncthreads();
    if (threadIdx.x < 64) {
        int n = threadIdx.x;
        float acc = 0.f;
        #pragma unroll
        for (int c = 0; c < 64; c++) { float v = s[c * 65 + n]; acc += v * v; }
        inv[n] = rsqrtf(acc + 1e-8f);
    }
    __syncthreads();
    float* dst = dst_ + ((size_t)b * N + n0) * 64;
    for (int i = threadIdx.x; i < 4096; i += 256) {
        int n = i >> 6, c = i & 63;
        dst[n * 64 + c] = s[c * 65 + n] * inv[n];
    }
}

// ---------------- fused triple projection: out_m[b][n][o] = sum_c Wm[o][c]*P[b][c][n] ----------------
__global__ void __launch_bounds__(256) k_project3(
    const float* __restrict__ P,
    const float* __restrict__ Wa, const float* __restrict__ Wb, const float* __restrict__ Wc,
    float* __restrict__ oa, float* __restrict__ ob, float* __restrict__ oc, int N)
{
    extern __shared__ __align__(16) float psm[];
    float* s   = psm;            // [64][68] : s[n][c]
    float* Wsh = psm + 4352;     // 3 x [64][68]
    int b = blockIdx.y;
    int n0 = blockIdx.x * 64;
    int t = threadIdx.x;
    for (int i = t; i < 4096; i += 256) {
        int c = i >> 6, n = i & 63;
        s[n * 68 + c] = P[((size_t)b * 64 + c) * N + n0 + n];
    }
    for (int i = t; i < 4096; i += 256) Wsh[0 * 4352 + (i >> 6) * 68 + (i & 63)] = Wa[i];
    for (int i = t; i < 4096; i += 256) Wsh[1 * 4352 + (i >> 6) * 68 + (i & 63)] = Wb[i];
    for (int i = t; i < 4096; i += 256) Wsh[2 * 4352 + (i >> 6) * 68 + (i & 63)] = Wc[i];
    __syncthreads();
    int o = t & 63, nb = t >> 6;
    #pragma unroll 1
    for (int m = 0; m < 3; m++) {
        float acc[16];
        #pragma unroll
        for (int j = 0; j < 16; j++) acc[j] = 0.f;
        const float4* w4 = (const float4*)(Wsh + m * 4352 + o * 68);
        #pragma unroll
        for (int ci = 0; ci < 16; ci++) {
            float4 w = w4[ci];
            #pragma unroll
            for (int j = 0; j < 16; j++) {
                float4 v = ((const float4*)(s + (nb + 4 * j) * 68))[ci];
                acc[j] += w.x * v.x + w.y * v.y + w.z * v.z + w.w * v.w;
            }
        }
        float* dst = (m == 0 ? oa : (m == 1 ? ob : oc)) + ((size_t)b * N + n0) * 64;
        #pragma unroll
        for (int j = 0; j < 16; j++)
            dst[(nb + 4 * j) * 64 + o] = acc[j];
    }
}

// ---------------- cosine knn partial top-8 per split ----------------
__global__ void __launch_bounds__(128) k_cosknn() {
    __shared__ __align__(16) float s[64 * 68];
    int b = blockIdx.z, split = blockIdx.y;
    int q = blockIdx.x * 128 + threadIdx.x;
    ulonglong2 qr[16];
    const ulonglong2* qp = (const ulonglong2*)(g_f1n + ((size_t)b * N1 + q) * 64);
    #pragma unroll
    for (int i = 0; i < 16; i++) qr[i] = qp[i];
    float tv[8]; int ti[8];
    #pragma unroll
    for (int i = 0; i < 8; i++) { tv[i] = -1e30f; ti[i] = 0; }
    const int SPLITN = N2 / NSPLIT;
    int j0 = split * SPLITN;
    for (int tile = 0; tile < SPLITN / 64; tile++) {
        int jt = j0 + tile * 64;
        __syncthreads();
        for (int i = threadIdx.x; i < 4096; i += 128) {
            int cand = i >> 6, c = i & 63;
            s[cand * 68 + c] = g_f2n[((size_t)b * N2 + jt + cand) * 64 + c];
        }
        __syncthreads();
        for (int cc = 0; cc < 64; cc++) {
            const ulonglong2* cp = (const ulonglong2*)(s + cc * 68);
            unsigned long long a0 = 0ull, a1 = 0ull, a2 = 0ull, a3 = 0ull;
            #pragma unroll
            for (int i = 0; i < 16; i += 2) {
                ulonglong2 c2 = cp[i];
                fma2(a0, qr[i].x, c2.x);
                fma2(a1, qr[i].y, c2.y);
                ulonglong2 c3 = cp[i + 1];
                fma2(a2, qr[i + 1].x, c3.x);
                fma2(a3, qr[i + 1].y, c3.y);
            }
            float d = (hsum2(a0) + hsum2(a1)) + (hsum2(a2) + hsum2(a3));
            if (d > tv[7]) top8_insert(tv, ti, d, jt + cc);
        }
    }
    size_t base = (((size_t)b * N1 + q) * NSPLIT + split) * 8;
    #pragma unroll
    for (int t = 0; t < 8; t++) { g_cosv[base + t] = tv[t]; g_cosi[base + t] = ti[t]; }
}

// ---------------- euclidean knn partial top-8 per split ----------------
__global__ void __launch_bounds__(128) k_eucknn(const float* __restrict__ xyz1, const float* __restrict__ xyz2) {
    __shared__ float sx[1024], sy[1024], sz[1024];
    int b = blockIdx.z, split = blockIdx.y;
    int q = blockIdx.x * 128 + threadIdx.x;
    int j0 = split * 1024;
    const float* x2 = xyz2 + (size_t)b * 3 * N2;
    for (int i = threadIdx.x; i < 1024; i += 128) {
        sx[i] = x2[j0 + i]; sy[i] = x2[N2 + j0 + i]; sz[i] = x2[2 * N2 + j0 + i];
    }
    __syncthreads();
    const float* x1 = xyz1 + (size_t)b * 3 * N1;
    float qx = x1[q], qy = x1[N1 + q], qz = x1[2 * N1 + q];
    float tv[8]; int ti[8];
    #pragma unroll
    for (int i = 0; i < 8; i++) { tv[i] = -1e30f; ti[i] = 0; }
    for (int cc = 0; cc < 1024; cc++) {
        float dx = sx[cc] - qx, dy = sy[cc] - qy, dz = sz[cc] - qz;
        float d = -(dx * dx + dy * dy + dz * dz);
        if (d > tv[7]) top8_insert(tv, ti, d, j0 + cc);
    }
    size_t base = (((size_t)b * N1 + q) * NSPLIT + split) * 8;
    #pragma unroll
    for (int t = 0; t < 8; t++) { g_eucv[base + t] = tv[t]; g_euci[base + t] = ti[t]; }
}

// ---------------- merge split partials -> idx[q][16] ----------------
__global__ void k_merge() {
    int q = blockIdx.x * 256 + threadIdx.x;
    if (q >= BB * N1) return;
    size_t base = (size_t)q * (NSPLIT * 8);
    float tv[8]; int ti[8];
    #pragma unroll
    for (int i = 0; i < 8; i++) { tv[i] = -1e30f; ti[i] = 0; }
    for (int i = 0; i < NSPLIT * 8; i++) {
        float v = g_cosv[base + i];
        if (v > tv[7]) top8_insert(tv, ti, v, g_cosi[base + i]);
    }
    #pragma unroll
    for (int t = 0; t < 8; t++) g_idx[q * KSEL + t] = ti[t];
    #pragma unroll
    for (int i = 0; i < 8; i++) { tv[i] = -1e30f; ti[i] = 0; }
    for (int i = 0; i < NSPLIT * 8; i++) {
        float v = g_eucv[base + i];
        if (v > tv[7]) top8_insert(tv, ti, v, g_euci[base + i]);
    }
    #pragma unroll
    for (int t = 0; t < 8; t++) g_idx[q * KSEL + 8 + t] = ti[t];
}

// ---------------- fused GRU-mapping MLP (k-bulk staging) ----------------
// block = 256 threads = 4 groups of 64; group handles one query, thread = channel o.
// All K=16 neighbors processed per stage; weight row register-resident per pass.
// Barriers: 5 named per group (vs 80 in the per-k pipeline).
#define GBAR(g) asm volatile("bar.sync %0, 64;" :: "r"((g) + 1) : "memory")

__global__ void __launch_bounds__(256) k_mlp(
    const float* __restrict__ xyz1, const float* __restrict__ xyz2,
    const float* __restrict__ Wr0, const float* __restrict__ br0,
    const float* __restrict__ Wr1, const float* __restrict__ br1,
    const float* __restrict__ Wr2, const float* __restrict__ br2,
    const float* __restrict__ Wz0, const float* __restrict__ bz0,
    const float* __restrict__ Wz1, const float* __restrict__ bz1,
    const float* __restrict__ Wz2, const float* __restrict__ bz2,
    const float* __restrict__ Wh0, const float* __restrict__ bh0,
    const float* __restrict__ Wh1, const float* __restrict__ bh1,
    const float* __restrict__ Wh2, const float* __restrict__ bh2,
    float* __restrict__ out)
{
    extern __shared__ __align__(16) float dsm[];
    // weights: 6 matrices, rows padded to 68 floats
    float* WR1 = dsm;
    float* WR2 = WR1 + 4352;
    float* WZ1 = WR2 + 4352;
    float* WZ2 = WZ1 + 4352;
    float* WH1 = WZ2 + 4352;
    float* WH2 = WH1 + 4352;
    float* GBUF = WH2 + 4352;        // 4 groups x 4 buffers x 16*64
    __shared__ int sIdx[4 * 16];

    int tid = threadIdx.x;
    int g = tid >> 6, o = tid & 63;

    // load 6 weight matrices into padded smem rows
    {
        const float* Wsrc[6] = {Wr1, Wr2, Wz1, Wz2, Wh1, Wh2};
        for (int i = tid; i < 6 * 4096; i += 256) {
            int m = i >> 12, r = i & 4095;
            dsm[m * 4352 + (r >> 6) * 68 + (r & 63)] = Wsrc[m][r];
        }
    }

    int q = blockIdx.x * 4 + g;
    int b = q >> 12, n = q & 4095;
    if (o < 16) sIdx[g * 16 + o] = g_idx[q * KSEL + o];

    float wr0x = Wr0[o * 3], wr0y = Wr0[o * 3 + 1], wr0z = Wr0[o * 3 + 2];
    float wz0x = Wz0[o * 3], wz0y = Wz0[o * 3 + 1], wz0z = Wz0[o * 3 + 2];
    float wh0x = Wh0[o * 3], wh0y = Wh0[o * 3 + 1], wh0z = Wh0[o * 3 + 2];
    float br0o = br0[o], br1o = br1[o], br2o = br2[o];
    float bz0o = bz0[o], bz1o = bz1[o], bz2o = bz2[o];
    float bh0o = bh0[o], bh1o = bh1[o], bh2o = bh2[o];
    size_t nb = (size_t)b * N1 + n;
    float gp1ro = g_gp1r[nb * 64 + o];
    float gp1zo = g_gp1z[nb * 64 + o];
    float p1oo  = g_p1o [nb * 64 + o];
    float x1x = xyz1[(b * 3 + 0) * N1 + n];
    float x1y = xyz1[(b * 3 + 1) * N1 + n];
    float x1z = xyz1[(b * 3 + 2) * N1 + n];

    float* T  = GBUF + g * 4096;          // t0[k][o], later reused for v0
    float* U  = T + 1024;                 // u0[k][o]
    float* V  = U + 1024;                 // h partial (un-activated)
    float* Bv = V + 1024;                 // t1[k][o], later zmax/hmax vectors

    __syncthreads();   // weights + sIdx ready

    // ---- Stage A: elementwise layer-0 for all k ----
    #pragma unroll 2
    for (int k = 0; k < KSEL; k++) {
        int j = sIdx[g * 16 + k];
        size_t gb = ((size_t)b * N2 + j) * 64 + o;
        float gr  = g_p2r [gb];
        float gro = g_p2ro[gb];
        float gz  = g_p2z [gb];
        float dx = __ldg(&xyz2[(b * 3 + 0) * N2 + j]) - x1x;
        float dy = __ldg(&xyz2[(b * 3 + 1) * N2 + j]) - x1y;
        float dz = __ldg(&xyz2[(b * 3 + 2) * N2 + j]) - x1z;
        T[k * 64 + o] = leaky(fmaf(wr0x, dx, fmaf(wr0y, dy, fmaf(wr0z, dz, br0o + gp1ro + gr))));
        U[k * 64 + o] = leaky(fmaf(wz0x, dx, fmaf(wz0y, dy, fmaf(wz0z, dz, bz0o + gp1zo + gro))));
        V[k * 64 + o] = fmaf(wh0x, dx, fmaf(wh0y, dy, fmaf(wh0z, dz, bh0o + gz)));
    }
    GBAR(g);

    ulonglong2 w[16];
    // ---- pass WR1: t1[k] = leaky(WR1 t0[k] + br1) ----
    loadrow(WR1, o, w);
    #pragma unroll 1
    for (int k = 0; k < KSEL; k++)
        Bv[k * 64 + o] = leaky(dotv64(w, T + k * 64) + br1o);
    // ---- pass WZ1: zmax = max_k leaky(WZ1 u0[k] + bz1) ----
    loadrow(WZ1, o, w);
    float zmax = -1e30f;
    #pragma unroll 1
    for (int k = 0; k < KSEL; k++)
        zmax = fmaxf(zmax, leaky(dotv64(w, U + k * 64) + bz1o));
    GBAR(g);

    // ---- pass WR2: r[k] = sigm(WR2 t1[k] + br2); v0[k][o] = leaky(Vpartial + r*p1o) ----
    loadrow(WR2, o, w);
    #pragma unroll 1
    for (int k = 0; k < KSEL; k++) {
        float r = sigm(dotv64(w, Bv + k * 64) + br2o);
        V[k * 64 + o] = leaky(fmaf(r, p1oo, V[k * 64 + o]));
    }
    GBAR(g);

    // ---- pass WH1: hmax = max_k leaky(WH1 v0[k] + bh1) ----
    loadrow(WH1, o, w);
    float hmax = -1e30f;
    #pragma unroll 1
    for (int k = 0; k < KSEL; k++)
        hmax = fmaxf(hmax, leaky(dotv64(w, V + k * 64) + bh1o));

    Bv[o] = zmax;
    Bv[64 + o] = hmax;
    GBAR(g);

    // ---- final layer ----
    loadrow(WZ2, o, w);
    float z = sigm(dotv64(w, Bv) + bz2o);
    loadrow(WH2, o, w);
    float h = leaky(dotv64(w, Bv + 64) + bh2o);
    out[((size_t)b * 64 + o) * N1 + n] = (1.f - z) * p1oo + z * h;
}

// ---------------- launch ----------------
extern "C" void kernel_launch(void* const* d_in, const int* in_sizes, int n_in,
                              void* d_out, int out_size) {
    (void)in_sizes; (void)n_in; (void)out_size;
    const float* xyz1    = (const float*)d_in[0];
    const float* xyz2    = (const float*)d_in[1];
    const float* points1 = (const float*)d_in[2];
    const float* points2 = (const float*)d_in[3];
    const float* knn1    = (const float*)d_in[4];
    const float* knn2    = (const float*)d_in[5];
    const float* Wfr   = (const float*)d_in[6];
    const float* Wfro  = (const float*)d_in[7];
    const float* Wfz   = (const float*)d_in[8];
    const float* Wfr2  = (const float*)d_in[9];
    const float* Wfro2 = (const float*)d_in[10];
    const float* Wfz2  = (const float*)d_in[11];
    const float* Wr0 = (const float*)d_in[12]; const float* br0 = (const float*)d_in[13];
    const float* Wr1 = (const float*)d_in[14]; const float* br1 = (const float*)d_in[15];
    const float* Wr2 = (const float*)d_in[16]; const float* br2 = (const float*)d_in[17];
    const float* Wz0 = (const float*)d_in[18]; const float* bz0 = (const float*)d_in[19];
    const float* Wz1 = (const float*)d_in[20]; const float* bz1 = (const float*)d_in[21];
    const float* Wz2 = (const float*)d_in[22]; const float* bz2 = (const float*)d_in[23];
    const float* Wh0 = (const float*)d_in[24]; const float* bh0 = (const float*)d_in[25];
    const float* Wh1 = (const float*)d_in[26]; const float* bh1 = (const float*)d_in[27];
    const float* Wh2 = (const float*)d_in[28]; const float* bh2 = (const float*)d_in[29];
    float* out = (float*)d_out;

    float *f1n, *f2n, *p2r, *p2ro, *p2z, *gp1r, *gp1z, *p1o;
    cudaGetSymbolAddress((void**)&f1n,  g_f1n);
    cudaGetSymbolAddress((void**)&f2n,  g_f2n);
    cudaGetSymbolAddress((void**)&p2r,  g_p2r);
    cudaGetSymbolAddress((void**)&p2ro, g_p2ro);
    cudaGetSymbolAddress((void**)&p2z,  g_p2z);
    cudaGetSymbolAddress((void**)&gp1r, g_gp1r);
    cudaGetSymbolAddress((void**)&gp1z, g_gp1z);
    cudaGetSymbolAddress((void**)&p1o,  g_p1o);

    const int PROJ3_SMEM = 4 * 4352 * 4;    // 69632 B
    const int MLP_SMEM   = (6 * 4352 + 4 * 4 * 1024) * 4;  // 169984 B
    static bool attr_done = false;
    if (!attr_done) {
        cudaFuncSetAttribute(k_project3, cudaFuncAttributeMaxDynamicSharedMemorySize, PROJ3_SMEM);
        cudaFuncSetAttribute(k_mlp, cudaFuncAttributeMaxDynamicSharedMemorySize, MLP_SMEM);
        attr_done = true;
    }

    // normalize knn features (transposed layouts)
    k_normalize<<<dim3(N1 / 64, BB), 256>>>(knn1, f1n, N1);
    k_normalize<<<dim3(N2 / 64, BB), 256>>>(knn2, f2n, N2);

    // fused 1x1-conv projections (3 outputs per input)
    k_project3<<<dim3(N2 / 64, BB), 256, PROJ3_SMEM>>>(points2, Wfr2, Wfro2, Wfz2, p2r, p2ro, p2z, N2);
    k_project3<<<dim3(N1 / 64, BB), 256, PROJ3_SMEM>>>(points1, Wfr,  Wfz,   Wfro, gp1r, gp1z, p1o, N1);

    // knn selection
    k_cosknn<<<dim3(N1 / 128, NSPLIT, BB), 128>>>();
    k_eucknn<<<dim3(N1 / 128, NSPLIT, BB), 128>>>(xyz1, xyz2);
    k_merge<<<(BB * N1) / 256, 256>>>();

    // fused GRU MLP (k-bulk staging)
    k_mlp<<<(BB * N1) / 4, 256, MLP_SMEM>>>(
        xyz1, xyz2,
        Wr0, br0, Wr1, br1, Wr2, br2,
        Wz0, bz0, Wz1, bz1, Wz2, bz2,
        Wh0, bh0, Wh1, bh1, Wh2, bh2,
        out);
}

// round 9
// speedup vs baseline: 1.7654x; 1.7654x over previous
#include <cuda_runtime.h>
#include <cstdint>

#define BB 2
#define N1 4096
#define N2 8192
#define NSPLIT 8
#define KSEL 16

// ---------------- scratch (__device__ globals: allowed) ----------------
__device__ __align__(16) float g_f1n [BB*N1*64];
__device__ __align__(16) float g_f2n [BB*N2*64];
__device__ __align__(16) float g_p2r [BB*N2*64];
__device__ __align__(16) float g_p2ro[BB*N2*64];
__device__ __align__(16) float g_p2z [BB*N2*64];
__device__ __align__(16) float g_gp1r[BB*N1*64];
__device__ __align__(16) float g_gp1z[BB*N1*64];
__device__ __align__(16) float g_p1o [BB*N1*64];
__device__ float g_cosv[BB*N1*NSPLIT*8];
__device__ int   g_cosi[BB*N1*NSPLIT*8];
__device__ float g_eucv[BB*N1*NSPLIT*8];
__device__ int   g_euci[BB*N1*NSPLIT*8];
__device__ int   g_idx [BB*N1*KSEL];

// ---------------- helpers ----------------
__device__ __forceinline__ void fma2(unsigned long long& d, unsigned long long a, unsigned long long b) {
    asm("fma.rn.f32x2 %0, %1, %2, %0;" : "+l"(d) : "l"(a), "l"(b));
}
__device__ __forceinline__ float hsum2(unsigned long long v) {
    return __uint_as_float((unsigned)v) + __uint_as_float((unsigned)(v >> 32));
}
__device__ __forceinline__ float leaky(float x) { return fmaxf(x, 0.1f * x); }
__device__ __forceinline__ float sigm(float x) { return 1.f / (1.f + __expf(-x)); }

__device__ __forceinline__ void top8_insert(float (&tv)[8], int (&ti)[8], float v, int j) {
    #pragma unroll
    for (int t = 0; t < 8; t++) {
        if (v > tv[t]) { float fv = tv[t]; int fj = ti[t]; tv[t] = v; ti[t] = j; v = fv; j = fj; }
    }
}

// load one 64-float weight row (68-float padded) from smem into registers
__device__ __forceinline__ void loadrow(const float* __restrict__ W, int o, ulonglong2 (&w)[16]) {
    const ulonglong2* p = (const ulonglong2*)(W + o * 68);
    #pragma unroll
    for (int i = 0; i < 16; i++) w[i] = p[i];
}
// dot of register weight row with a 64-float smem vector (broadcast reads)
__device__ __forceinline__ float dotv64(const ulonglong2 (&w)[16], const float* __restrict__ v) {
    const ulonglong2* v2 = (const ulonglong2*)v;
    unsigned long long a0 = 0ull, a1 = 0ull, a2 = 0ull, a3 = 0ull;
    #pragma unroll
    for (int i = 0; i < 16; i += 2) {
        ulonglong2 x = v2[i];
        fma2(a0, w[i].x, x.x); fma2(a1, w[i].y, x.y);
        ulonglong2 y = v2[i + 1];
        fma2(a2, w[i + 1].x, y.x); fma2(a3, w[i + 1].y, y.y);
    }
    return (hsum2(a0) + hsum2(a1)) + (hsum2(a2) + hsum2(a3));
}
// dot of a gmem weight row (64 consecutive floats) with a 64-float smem vector
__device__ __forceinline__ float gdot64(const float* __restrict__ Wrow, const float* __restrict__ v) {
    const float4* w4 = (const float4*)Wrow;
    const float4* v4 = (const float4*)v;
    float a0 = 0.f, a1 = 0.f, a2 = 0.f, a3 = 0.f;
    #pragma unroll
    for (int i = 0; i < 16; i += 4) {
        float4 w = __ldg(&w4[i]);     float4 x = v4[i];
        a0 += w.x * x.x + w.y * x.y + w.z * x.z + w.w * x.w;
        float4 w1 = __ldg(&w4[i + 1]); float4 x1 = v4[i + 1];
        a1 += w1.x * x1.x + w1.y * x1.y + w1.z * x1.z + w1.w * x1.w;
        float4 w2 = __ldg(&w4[i + 2]); float4 x2 = v4[i + 2];
        a2 += w2.x * x2.x + w2.y * x2.y + w2.z * x2.z + w2.w * x2.w;
        float4 w3 = __ldg(&w4[i + 3]); float4 x3 = v4[i + 3];
        a3 += w3.x * x3.x + w3.y * x3.y + w3.z * x3.z + w3.w * x3.w;
    }
    return (a0 + a1) + (a2 + a3);
}

// ---------------- normalize: dst[b][n][c] = src[b][c][n] * rsqrt(sumsq+1e-8) ----------------
__global__ void k_normalize(const float* __restrict__ src_, float* __restrict__ dst_, int N) {
    __shared__ float s[64 * 65];
    __shared__ float inv[64];
    int b = blockIdx.y;
    int n0 = blockIdx.x * 64;
    const float* src = src_ + (size_t)b * 64 * N;
    for (int i = threadIdx.x; i < 4096; i += 256) {
        int c = i >> 6, n = i & 63;
        s[c * 65 + n] = src[(size_t)c * N + n0 + n];
    }
    __syncthreads();
    if (threadIdx.x < 64) {
        int n = threadIdx.x;
        float acc = 0.f;
        #pragma unroll
        for (int c = 0; c < 64; c++) { float v = s[c * 65 + n]; acc += v * v; }
        inv[n] = rsqrtf(acc + 1e-8f);
    }
    __syncthreads();
    float* dst = dst_ + ((size_t)b * N + n0) * 64;
    for (int i = threadIdx.x; i < 4096; i += 256) {
        int n = i >> 6, c = i & 63;
        dst[n * 64 + c] = s[c * 65 + n] * inv[n];
    }
}

// ---------------- project (R6 proven version): out[b][n][o] = sum_c W[o][c]*P[b][c][n] ----------------
__global__ void __launch_bounds__(256) k_project(const float* __restrict__ P, const float* __restrict__ W,
                                                 float* __restrict__ out, int N) {
    __shared__ __align__(16) float s[64 * 68];    // s[n][c]
    __shared__ __align__(16) float Wsh[64 * 68];  // Wsh[o][c]
    int b = blockIdx.y;
    int n0 = blockIdx.x * 64;
    int t = threadIdx.x;
    for (int i = t; i < 4096; i += 256) {
        int c = i >> 6, n = i & 63;
        s[n * 68 + c] = P[((size_t)b * 64 + c) * N + n0 + n];
        Wsh[(i >> 6) * 68 + (i & 63)] = W[i];
    }
    __syncthreads();
    int o = t & 63, nb = t >> 6;
    float acc[16];
    #pragma unroll
    for (int j = 0; j < 16; j++) acc[j] = 0.f;
    const float4* w4 = (const float4*)(Wsh + o * 68);
    #pragma unroll
    for (int ci = 0; ci < 16; ci++) {
        float4 w = w4[ci];
        #pragma unroll
        for (int j = 0; j < 16; j++) {
            float4 v = ((const float4*)(s + (nb + 4 * j) * 68))[ci];
            acc[j] += w.x * v.x + w.y * v.y + w.z * v.z + w.w * v.w;
        }
    }
    float* dst = out + ((size_t)b * N + n0) * 64;
    #pragma unroll
    for (int j = 0; j < 16; j++)
        dst[(nb + 4 * j) * 64 + o] = acc[j];
}

// ---------------- cosine knn partial top-8 per split ----------------
__global__ void __launch_bounds__(128) k_cosknn() {
    __shared__ __align__(16) float s[64 * 68];
    int b = blockIdx.z, split = blockIdx.y;
    int q = blockIdx.x * 128 + threadIdx.x;
    ulonglong2 qr[16];
    const ulonglong2* qp = (const ulonglong2*)(g_f1n + ((size_t)b * N1 + q) * 64);
    #pragma unroll
    for (int i = 0; i < 16; i++) qr[i] = qp[i];
    float tv[8]; int ti[8];
    #pragma unroll
    for (int i = 0; i < 8; i++) { tv[i] = -1e30f; ti[i] = 0; }
    const int SPLITN = N2 / NSPLIT;
    int j0 = split * SPLITN;
    for (int tile = 0; tile < SPLITN / 64; tile++) {
        int jt = j0 + tile * 64;
        __syncthreads();
        for (int i = threadIdx.x; i < 4096; i += 128) {
            int cand = i >> 6, c = i & 63;
            s[cand * 68 + c] = g_f2n[((size_t)b * N2 + jt + cand) * 64 + c];
        }
        __syncthreads();
        for (int cc = 0; cc < 64; cc++) {
            const ulonglong2* cp = (const ulonglong2*)(s + cc * 68);
            unsigned long long a0 = 0ull, a1 = 0ull, a2 = 0ull, a3 = 0ull;
            #pragma unroll
            for (int i = 0; i < 16; i += 2) {
                ulonglong2 c2 = cp[i];
                fma2(a0, qr[i].x, c2.x);
                fma2(a1, qr[i].y, c2.y);
                ulonglong2 c3 = cp[i + 1];
                fma2(a2, qr[i + 1].x, c3.x);
                fma2(a3, qr[i + 1].y, c3.y);
            }
            float d = (hsum2(a0) + hsum2(a1)) + (hsum2(a2) + hsum2(a3));
            if (d > tv[7]) top8_insert(tv, ti, d, jt + cc);
        }
    }
    size_t base = (((size_t)b * N1 + q) * NSPLIT + split) * 8;
    #pragma unroll
    for (int t = 0; t < 8; t++) { g_cosv[base + t] = tv[t]; g_cosi[base + t] = ti[t]; }
}

// ---------------- euclidean knn partial top-8 per split ----------------
__global__ void __launch_bounds__(128) k_eucknn(const float* __restrict__ xyz1, const float* __restrict__ xyz2) {
    __shared__ float sx[1024], sy[1024], sz[1024];
    int b = blockIdx.z, split = blockIdx.y;
    int q = blockIdx.x * 128 + threadIdx.x;
    int j0 = split * 1024;
    const float* x2 = xyz2 + (size_t)b * 3 * N2;
    for (int i = threadIdx.x; i < 1024; i += 128) {
        sx[i] = x2[j0 + i]; sy[i] = x2[N2 + j0 + i]; sz[i] = x2[2 * N2 + j0 + i];
    }
    __syncthreads();
    const float* x1 = xyz1 + (size_t)b * 3 * N1;
    float qx = x1[q], qy = x1[N1 + q], qz = x1[2 * N1 + q];
    float tv[8]; int ti[8];
    #pragma unroll
    for (int i = 0; i < 8; i++) { tv[i] = -1e30f; ti[i] = 0; }
    for (int cc = 0; cc < 1024; cc++) {
        float dx = sx[cc] - qx, dy = sy[cc] - qy, dz = sz[cc] - qz;
        float d = -(dx * dx + dy * dy + dz * dz);
        if (d > tv[7]) top8_insert(tv, ti, d, j0 + cc);
    }
    size_t base = (((size_t)b * N1 + q) * NSPLIT + split) * 8;
    #pragma unroll
    for (int t = 0; t < 8; t++) { g_eucv[base + t] = tv[t]; g_euci[base + t] = ti[t]; }
}

// ---------------- merge split partials -> idx[q][16] ----------------
__global__ void k_merge() {
    int q = blockIdx.x * 256 + threadIdx.x;
    if (q >= BB * N1) return;
    size_t base = (size_t)q * (NSPLIT * 8);
    float tv[8]; int ti[8];
    #pragma unroll
    for (int i = 0; i < 8; i++) { tv[i] = -1e30f; ti[i] = 0; }
    for (int i = 0; i < NSPLIT * 8; i++) {
        float v = g_cosv[base + i];
        if (v > tv[7]) top8_insert(tv, ti, v, g_cosi[base + i]);
    }
    #pragma unroll
    for (int t = 0; t < 8; t++) g_idx[q * KSEL + t] = ti[t];
    #pragma unroll
    for (int i = 0; i < 8; i++) { tv[i] = -1e30f; ti[i] = 0; }
    for (int i = 0; i < NSPLIT * 8; i++) {
        float v = g_eucv[base + i];
        if (v > tv[7]) top8_insert(tv, ti, v, g_euci[base + i]);
    }
    #pragma unroll
    for (int t = 0; t < 8; t++) g_idx[q * KSEL + 8 + t] = ti[t];
}

// ---------------- fused GRU-mapping MLP (k-bulk, 8 groups, 16 warps/SM) ----------------
// block = 512 threads = 8 groups of 64; group handles one query, thread = channel o.
// smem: 4 weight matrices (WR1,WR2,WZ1,WH1) + 3 k-buffers per group.
// Final layer (WZ2/WH2) reads weight rows from gmem (L1/L2-hot, 2 vectors only).
#define GBAR(g) asm volatile("bar.sync %0, 64;" :: "r"((g) + 1) : "memory")

__global__ void __launch_bounds__(512, 1) k_mlp(
    const float* __restrict__ xyz1, const float* __restrict__ xyz2,
    const float* __restrict__ Wr0, const float* __restrict__ br0,
    const float* __restrict__ Wr1, const float* __restrict__ br1,
    const float* __restrict__ Wr2, const float* __restrict__ br2,
    const float* __restrict__ Wz0, const float* __restrict__ bz0,
    const float* __restrict__ Wz1, const float* __restrict__ bz1,
    const float* __restrict__ Wz2, const float* __restrict__ bz2,
    const float* __restrict__ Wh0, const float* __restrict__ bh0,
    const float* __restrict__ Wh1, const float* __restrict__ bh1,
    const float* __restrict__ Wh2, const float* __restrict__ bh2,
    float* __restrict__ out)
{
    extern __shared__ __align__(16) float dsm[];
    float* WR1 = dsm;                 // 4 matrices, rows padded to 68
    float* WR2 = WR1 + 4352;
    float* WZ1 = WR2 + 4352;
    float* WH1 = WZ1 + 4352;
    float* GBUF = WH1 + 4352;         // 8 groups x 3 buffers x 16*64
    __shared__ int sIdx[8 * 16];

    int tid = threadIdx.x;
    int g = tid >> 6, o = tid & 63;

    // load 4 weight matrices into padded smem rows
    {
        const float* Wsrc[4] = {Wr1, Wr2, Wz1, Wh1};
        for (int i = tid; i < 4 * 4096; i += 512) {
            int m = i >> 12, r = i & 4095;
            dsm[m * 4352 + (r >> 6) * 68 + (r & 63)] = Wsrc[m][r];
        }
    }

    int q = blockIdx.x * 8 + g;
    int b = q >> 12, n = q & 4095;
    if (o < 16) sIdx[g * 16 + o] = g_idx[q * KSEL + o];

    float wr0x = Wr0[o * 3], wr0y = Wr0[o * 3 + 1], wr0z = Wr0[o * 3 + 2];
    float wz0x = Wz0[o * 3], wz0y = Wz0[o * 3 + 1], wz0z = Wz0[o * 3 + 2];
    float wh0x = Wh0[o * 3], wh0y = Wh0[o * 3 + 1], wh0z = Wh0[o * 3 + 2];
    float br0o = br0[o], br1o = br1[o], br2o = br2[o];
    float bz0o = bz0[o], bz1o = bz1[o];
    float bh0o = bh0[o], bh1o = bh1[o];
    float bz2o = bz2[o], bh2o = bh2[o];
    size_t nb = (size_t)b * N1 + n;
    float gp1ro = g_gp1r[nb * 64 + o];
    float gp1zo = g_gp1z[nb * 64 + o];
    float p1oo  = g_p1o [nb * 64 + o];
    float x1x = xyz1[(b * 3 + 0) * N1 + n];
    float x1y = xyz1[(b * 3 + 1) * N1 + n];
    float x1z = xyz1[(b * 3 + 2) * N1 + n];

    float* T = GBUF + g * 3072;   // t0[k][o]; later zmax/hmax vectors
    float* U = T + 1024;          // u0[k][o]; later t1[k][o]
    float* V = U + 1024;          // h partial, then v0[k][o]

    __syncthreads();   // weights + sIdx ready

    // ---- Stage A: elementwise layer-0 for all k ----
    #pragma unroll 2
    for (int k = 0; k < KSEL; k++) {
        int j = sIdx[g * 16 + k];
        size_t gb = ((size_t)b * N2 + j) * 64 + o;
        float gr  = g_p2r [gb];
        float gro = g_p2ro[gb];
        float gz  = g_p2z [gb];
        float dx = __ldg(&xyz2[(b * 3 + 0) * N2 + j]) - x1x;
        float dy = __ldg(&xyz2[(b * 3 + 1) * N2 + j]) - x1y;
        float dz = __ldg(&xyz2[(b * 3 + 2) * N2 + j]) - x1z;
        T[k * 64 + o] = leaky(fmaf(wr0x, dx, fmaf(wr0y, dy, fmaf(wr0z, dz, br0o + gp1ro + gr))));
        U[k * 64 + o] = leaky(fmaf(wz0x, dx, fmaf(wz0y, dy, fmaf(wz0z, dz, bz0o + gp1zo + gro))));
        V[k * 64 + o] = fmaf(wh0x, dx, fmaf(wh0y, dy, fmaf(wh0z, dz, bh0o + gz)));
    }
    GBAR(g);   // (1) T,U,V visible

    ulonglong2 w[16];
    float t1k[KSEL];
    // ---- pass WR1: t1[k] (held in regs) ----
    loadrow(WR1, o, w);
    #pragma unroll 2
    for (int k = 0; k < KSEL; k++)
        t1k[k] = leaky(dotv64(w, T + k * 64) + br1o);
    // ---- pass WZ1: zmax ----
    loadrow(WZ1, o, w);
    float zmax = -1e30f;
    #pragma unroll 2
    for (int k = 0; k < KSEL; k++)
        zmax = fmaxf(zmax, leaky(dotv64(w, U + k * 64) + bz1o));
    GBAR(g);   // (2) all done reading T,U
    #pragma unroll
    for (int k = 0; k < KSEL; k++)
        U[k * 64 + o] = t1k[k];
    GBAR(g);   // (3) t1 visible
    // ---- pass WR2: r[k], update V in place ----
    loadrow(WR2, o, w);
    #pragma unroll 2
    for (int k = 0; k < KSEL; k++) {
        float r = sigm(dotv64(w, U + k * 64) + br2o);
        V[k * 64 + o] = leaky(fmaf(r, p1oo, V[k * 64 + o]));
    }
    GBAR(g);   // (4) V updates visible
    // ---- pass WH1: hmax ----
    loadrow(WH1, o, w);
    float hmax = -1e30f;
    #pragma unroll 2
    for (int k = 0; k < KSEL; k++)
        hmax = fmaxf(hmax, leaky(dotv64(w, V + k * 64) + bh1o));

    T[o] = zmax;
    T[64 + o] = hmax;
    GBAR(g);   // (5) zmax/hmax vectors visible

    // ---- final layer: weights from gmem (L1-hot across groups) ----
    float z = sigm(gdot64(Wz2 + o * 64, T) + bz2o);
    float h = leaky(gdot64(Wh2 + o * 64, T + 64) + bh2o);
    out[((size_t)b * 64 + o) * N1 + n] = (1.f - z) * p1oo + z * h;
}

// ---------------- launch ----------------
extern "C" void kernel_launch(void* const* d_in, const int* in_sizes, int n_in,
                              void* d_out, int out_size) {
    (void)in_sizes; (void)n_in; (void)out_size;
    const float* xyz1    = (const float*)d_in[0];
    const float* xyz2    = (const float*)d_in[1];
    const float* points1 = (const float*)d_in[2];
    const float* points2 = (const float*)d_in[3];
    const float* knn1    = (const float*)d_in[4];
    const float* knn2    = (const float*)d_in[5];
    const float* Wfr   = (const float*)d_in[6];
    const float* Wfro  = (const float*)d_in[7];
    const float* Wfz   = (const float*)d_in[8];
    const float* Wfr2  = (const float*)d_in[9];
    const float* Wfro2 = (const float*)d_in[10];
    const float* Wfz2  = (const float*)d_in[11];
    const float* Wr0 = (const float*)d_in[12]; const float* br0 = (const float*)d_in[13];
    const float* Wr1 = (const float*)d_in[14]; const float* br1 = (const float*)d_in[15];
    const float* Wr2 = (const float*)d_in[16]; const float* br2 = (const float*)d_in[17];
    const float* Wz0 = (const float*)d_in[18]; const float* bz0 = (const float*)d_in[19];
    const float* Wz1 = (const float*)d_in[20]; const float* bz1 = (const float*)d_in[21];
    const float* Wz2 = (const float*)d_in[22]; const float* bz2 = (const float*)d_in[23];
    const float* Wh0 = (const float*)d_in[24]; const float* bh0 = (const float*)d_in[25];
    const float* Wh1 = (const float*)d_in[26]; const float* bh1 = (const float*)d_in[27];
    const float* Wh2 = (const float*)d_in[28]; const float* bh2 = (const float*)d_in[29];
    float* out = (float*)d_out;

    float *f1n, *f2n, *p2r, *p2ro, *p2z, *gp1r, *gp1z, *p1o;
    cudaGetSymbolAddress((void**)&f1n,  g_f1n);
    cudaGetSymbolAddress((void**)&f2n,  g_f2n);
    cudaGetSymbolAddress((void**)&p2r,  g_p2r);
    cudaGetSymbolAddress((void**)&p2ro, g_p2ro);
    cudaGetSymbolAddress((void**)&p2z,  g_p2z);
    cudaGetSymbolAddress((void**)&gp1r, g_gp1r);
    cudaGetSymbolAddress((void**)&gp1z, g_gp1z);
    cudaGetSymbolAddress((void**)&p1o,  g_p1o);

    const int MLP_SMEM = (4 * 4352 + 8 * 3 * 1024) * 4;  // 167936 B
    cudaFuncSetAttribute(k_mlp, cudaFuncAttributeMaxDynamicSharedMemorySize, MLP_SMEM);

    // normalize knn features (transposed layouts)
    k_normalize<<<dim3(N1 / 64, BB), 256>>>(knn1, f1n, N1);
    k_normalize<<<dim3(N2 / 64, BB), 256>>>(knn2, f2n, N2);

    // 6 fused 1x1-conv projections (proven low-reg version)
    k_project<<<dim3(N2 / 64, BB), 256>>>(points2, Wfr2,  p2r,  N2);
    k_project<<<dim3(N2 / 64, BB), 256>>>(points2, Wfro2, p2ro, N2);
    k_project<<<dim3(N2 / 64, BB), 256>>>(points2, Wfz2,  p2z,  N2);
    k_project<<<dim3(N1 / 64, BB), 256>>>(points1, Wfr,   gp1r, N1);
    k_project<<<dim3(N1 / 64, BB), 256>>>(points1, Wfz,   gp1z, N1);
    k_project<<<dim3(N1 / 64, BB), 256>>>(points1, Wfro,  p1o,  N1);

    // knn selection
    k_cosknn<<<dim3(N1 / 128, NSPLIT, BB), 128>>>();
    k_eucknn<<<dim3(N1 / 128, NSPLIT, BB), 128>>>(xyz1, xyz2);
    k_merge<<<(BB * N1) / 256, 256>>>();

    // fused GRU MLP (k-bulk staging, 8 groups/block)
    k_mlp<<<(BB * N1) / 8, 512, MLP_SMEM>>>(
        xyz1, xyz2,
        Wr0, br0, Wr1, br1, Wr2, br2,
        Wz0, bz0, Wz1, bz1, Wz2, bz2,
        Wh0, bh0, Wh1, bh1, Wh2, bh2,
        out);
}

// round 10
// speedup vs baseline: 1.8989x; 1.0756x over previous
#include <cuda_runtime.h>
#include <cstdint>

#define BB 2
#define N1 4096
#define N2 8192
#define NSPLIT 8
#define KSEL 16

// ---------------- scratch (__device__ globals: allowed) ----------------
__device__ __align__(16) float g_f1n [BB*N1*64];
__device__ __align__(16) float g_f2n [BB*N2*64];
__device__ __align__(16) float g_p2r [BB*N2*64];
__device__ __align__(16) float g_p2ro[BB*N2*64];
__device__ __align__(16) float g_p2z [BB*N2*64];
__device__ __align__(16) float g_gp1r[BB*N1*64];
__device__ __align__(16) float g_gp1z[BB*N1*64];
__device__ __align__(16) float g_p1o [BB*N1*64];
__device__ float g_cosv[BB*N1*NSPLIT*8];
__device__ int   g_cosi[BB*N1*NSPLIT*8];
__device__ float g_eucv[BB*N1*NSPLIT*8];
__device__ int   g_euci[BB*N1*NSPLIT*8];
__device__ int   g_idx [BB*N1*KSEL];

// ---------------- helpers ----------------
__device__ __forceinline__ void fma2(unsigned long long& d, unsigned long long a, unsigned long long b) {
    asm("fma.rn.f32x2 %0, %1, %2, %0;" : "+l"(d) : "l"(a), "l"(b));
}
__device__ __forceinline__ float hsum2(unsigned long long v) {
    return __uint_as_float((unsigned)v) + __uint_as_float((unsigned)(v >> 32));
}
__device__ __forceinline__ float leaky(float x) { return fmaxf(x, 0.1f * x); }
__device__ __forceinline__ float sigm(float x) { return 1.f / (1.f + __expf(-x)); }

__device__ __forceinline__ void top8_insert(float (&tv)[8], int (&ti)[8], float v, int j) {
    #pragma unroll
    for (int t = 0; t < 8; t++) {
        if (v > tv[t]) { float fv = tv[t]; int fj = ti[t]; tv[t] = v; ti[t] = j; v = fv; j = fj; }
    }
}

// load one 64-float weight row (68-float padded) from smem into registers
__device__ __forceinline__ void loadrow(const float* __restrict__ W, int o, ulonglong2 (&w)[16]) {
    const ulonglong2* p = (const ulonglong2*)(W + o * 68);
    #pragma unroll
    for (int i = 0; i < 16; i++) w[i] = p[i];
}
// dot of register weight row with a 64-float smem vector (broadcast reads)
__device__ __forceinline__ float dotv64(const ulonglong2 (&w)[16], const float* __restrict__ v) {
    const ulonglong2* v2 = (const ulonglong2*)v;
    unsigned long long a0 = 0ull, a1 = 0ull, a2 = 0ull, a3 = 0ull;
    #pragma unroll
    for (int i = 0; i < 16; i += 2) {
        ulonglong2 x = v2[i];
        fma2(a0, w[i].x, x.x); fma2(a1, w[i].y, x.y);
        ulonglong2 y = v2[i + 1];
        fma2(a2, w[i + 1].x, y.x); fma2(a3, w[i + 1].y, y.y);
    }
    return (hsum2(a0) + hsum2(a1)) + (hsum2(a2) + hsum2(a3));
}
// dot of a gmem weight row (64 consecutive floats) with a 64-float smem vector
__device__ __forceinline__ float gdot64(const float* __restrict__ Wrow, const float* __restrict__ v) {
    const float4* w4 = (const float4*)Wrow;
    const float4* v4 = (const float4*)v;
    float a0 = 0.f, a1 = 0.f, a2 = 0.f, a3 = 0.f;
    #pragma unroll
    for (int i = 0; i < 16; i += 4) {
        float4 w = __ldg(&w4[i]);      float4 x = v4[i];
        a0 += w.x * x.x + w.y * x.y + w.z * x.z + w.w * x.w;
        float4 w1 = __ldg(&w4[i + 1]); float4 x1 = v4[i + 1];
        a1 += w1.x * x1.x + w1.y * x1.y + w1.z * x1.z + w1.w * x1.w;
        float4 w2 = __ldg(&w4[i + 2]); float4 x2 = v4[i + 2];
        a2 += w2.x * x2.x + w2.y * x2.y + w2.z * x2.z + w2.w * x2.w;
        float4 w3 = __ldg(&w4[i + 3]); float4 x3 = v4[i + 3];
        a3 += w3.x * x3.x + w3.y * x3.y + w3.z * x3.z + w3.w * x3.w;
    }
    return (a0 + a1) + (a2 + a3);
}

// ---------------- normalize both knn tensors in one launch ----------------
__global__ void k_norm_both(const float* __restrict__ knn1, const float* __restrict__ knn2,
                            float* __restrict__ f1n, float* __restrict__ f2n) {
    __shared__ float s[64 * 65];
    __shared__ float inv[64];
    int bx = blockIdx.x, b = blockIdx.y;
    const float* src; float* dst; int N, n0;
    if (bx < N1 / 64) { src = knn1; dst = f1n; N = N1; n0 = bx * 64; }
    else              { src = knn2; dst = f2n; N = N2; n0 = (bx - N1 / 64) * 64; }
    src += (size_t)b * 64 * N;
    for (int i = threadIdx.x; i < 4096; i += 256) {
        int c = i >> 6, n = i & 63;
        s[c * 65 + n] = src[(size_t)c * N + n0 + n];
    }
    __syncthreads();
    if (threadIdx.x < 64) {
        int n = threadIdx.x;
        float acc = 0.f;
        #pragma unroll
        for (int c = 0; c < 64; c++) { float v = s[c * 65 + n]; acc += v * v; }
        inv[n] = rsqrtf(acc + 1e-8f);
    }
    __syncthreads();
    dst += ((size_t)b * N + n0) * 64;
    for (int i = threadIdx.x; i < 4096; i += 256) {
        int n = i >> 6, c = i & 63;
        dst[n * 64 + c] = s[c * 65 + n] * inv[n];
    }
}

// ---------------- project (low-reg body), 3 weight variants via blockIdx.z ----------------
__global__ void __launch_bounds__(256) k_project_m(
    const float* __restrict__ P,
    const float* __restrict__ W0, const float* __restrict__ W1, const float* __restrict__ W2,
    float* __restrict__ o0, float* __restrict__ o1, float* __restrict__ o2, int N)
{
    __shared__ __align__(16) float s[64 * 68];    // s[n][c]
    __shared__ __align__(16) float Wsh[64 * 68];  // Wsh[o][c]
    int m = blockIdx.z;
    const float* W = (m == 0) ? W0 : ((m == 1) ? W1 : W2);
    float* out     = (m == 0) ? o0 : ((m == 1) ? o1 : o2);
    int b = blockIdx.y;
    int n0 = blockIdx.x * 64;
    int t = threadIdx.x;
    for (int i = t; i < 4096; i += 256) {
        int c = i >> 6, n = i & 63;
        s[n * 68 + c] = P[((size_t)b * 64 + c) * N + n0 + n];
        Wsh[(i >> 6) * 68 + (i & 63)] = W[i];
    }
    __syncthreads();
    int o = t & 63, nb = t >> 6;
    float acc[16];
    #pragma unroll
    for (int j = 0; j < 16; j++) acc[j] = 0.f;
    const float4* w4 = (const float4*)(Wsh + o * 68);
    #pragma unroll
    for (int ci = 0; ci < 16; ci++) {
        float4 w = w4[ci];
        #pragma unroll
        for (int j = 0; j < 16; j++) {
            float4 v = ((const float4*)(s + (nb + 4 * j) * 68))[ci];
            acc[j] += w.x * v.x + w.y * v.y + w.z * v.z + w.w * v.w;
        }
    }
    float* dst = out + ((size_t)b * N + n0) * 64;
    #pragma unroll
    for (int j = 0; j < 16; j++)
        dst[(nb + 4 * j) * 64 + o] = acc[j];
}

// ---------------- fused cos + euc knn partials: blockIdx.y 0..7 = cos split, 8..15 = euc split ----------------
__global__ void __launch_bounds__(128) k_knn_both(const float* __restrict__ xyz1, const float* __restrict__ xyz2) {
    __shared__ __align__(16) float sh[64 * 68];
    int b = blockIdx.z, yy = blockIdx.y;
    int q = blockIdx.x * 128 + threadIdx.x;

    if (yy < 8) {
        // ---- cosine ----
        int split = yy;
        ulonglong2 qr[16];
        const ulonglong2* qp = (const ulonglong2*)(g_f1n + ((size_t)b * N1 + q) * 64);
        #pragma unroll
        for (int i = 0; i < 16; i++) qr[i] = qp[i];
        float tv[8]; int ti[8];
        #pragma unroll
        for (int i = 0; i < 8; i++) { tv[i] = -1e30f; ti[i] = 0; }
        const int SPLITN = N2 / NSPLIT;
        int j0 = split * SPLITN;
        for (int tile = 0; tile < SPLITN / 64; tile++) {
            int jt = j0 + tile * 64;
            __syncthreads();
            for (int i = threadIdx.x; i < 4096; i += 128) {
                int cand = i >> 6, c = i & 63;
                sh[cand * 68 + c] = g_f2n[((size_t)b * N2 + jt + cand) * 64 + c];
            }
            __syncthreads();
            for (int cc = 0; cc < 64; cc++) {
                const ulonglong2* cp = (const ulonglong2*)(sh + cc * 68);
                unsigned long long a0 = 0ull, a1 = 0ull, a2 = 0ull, a3 = 0ull;
                #pragma unroll
                for (int i = 0; i < 16; i += 2) {
                    ulonglong2 c2 = cp[i];
                    fma2(a0, qr[i].x, c2.x);
                    fma2(a1, qr[i].y, c2.y);
                    ulonglong2 c3 = cp[i + 1];
                    fma2(a2, qr[i + 1].x, c3.x);
                    fma2(a3, qr[i + 1].y, c3.y);
                }
                float d = (hsum2(a0) + hsum2(a1)) + (hsum2(a2) + hsum2(a3));
                if (d > tv[7]) top8_insert(tv, ti, d, jt + cc);
            }
        }
        size_t base = (((size_t)b * N1 + q) * NSPLIT + split) * 8;
        #pragma unroll
        for (int t = 0; t < 8; t++) { g_cosv[base + t] = tv[t]; g_cosi[base + t] = ti[t]; }
    } else {
        // ---- euclidean ----
        int split = yy - 8;
        float* sx = sh; float* sy = sh + 1024; float* sz = sh + 2048;
        int j0 = split * 1024;
        const float* x2 = xyz2 + (size_t)b * 3 * N2;
        for (int i = threadIdx.x; i < 1024; i += 128) {
            sx[i] = x2[j0 + i]; sy[i] = x2[N2 + j0 + i]; sz[i] = x2[2 * N2 + j0 + i];
        }
        __syncthreads();
        const float* x1 = xyz1 + (size_t)b * 3 * N1;
        float qx = x1[q], qy = x1[N1 + q], qz = x1[2 * N1 + q];
        float tv[8]; int ti[8];
        #pragma unroll
        for (int i = 0; i < 8; i++) { tv[i] = -1e30f; ti[i] = 0; }
        for (int cc = 0; cc < 1024; cc++) {
            float dx = sx[cc] - qx, dy = sy[cc] - qy, dz = sz[cc] - qz;
            float d = -(dx * dx + dy * dy + dz * dz);
            if (d > tv[7]) top8_insert(tv, ti, d, j0 + cc);
        }
        size_t base = (((size_t)b * N1 + q) * NSPLIT + split) * 8;
        #pragma unroll
        for (int t = 0; t < 8; t++) { g_eucv[base + t] = tv[t]; g_euci[base + t] = ti[t]; }
    }
}

// ---------------- merge split partials -> idx[q][16] ----------------
__global__ void k_merge() {
    int q = blockIdx.x * 256 + threadIdx.x;
    if (q >= BB * N1) return;
    size_t base = (size_t)q * (NSPLIT * 8);
    float tv[8]; int ti[8];
    #pragma unroll
    for (int i = 0; i < 8; i++) { tv[i] = -1e30f; ti[i] = 0; }
    for (int i = 0; i < NSPLIT * 8; i++) {
        float v = g_cosv[base + i];
        if (v > tv[7]) top8_insert(tv, ti, v, g_cosi[base + i]);
    }
    #pragma unroll
    for (int t = 0; t < 8; t++) g_idx[q * KSEL + t] = ti[t];
    #pragma unroll
    for (int i = 0; i < 8; i++) { tv[i] = -1e30f; ti[i] = 0; }
    for (int i = 0; i < NSPLIT * 8; i++) {
        float v = g_eucv[base + i];
        if (v > tv[7]) top8_insert(tv, ti, v, g_euci[base + i]);
    }
    #pragma unroll
    for (int t = 0; t < 8; t++) g_idx[q * KSEL + 8 + t] = ti[t];
}

// ---------------- fused GRU-mapping MLP (k-bulk, 4 smem buffers, no local arrays) ----------------
// block = 512 threads = 8 groups of 64; group handles one query, thread = channel o.
#define GBAR(g) asm volatile("bar.sync %0, 64;" :: "r"((g) + 1) : "memory")

__global__ void __launch_bounds__(512, 1) k_mlp(
    const float* __restrict__ xyz1, const float* __restrict__ xyz2,
    const float* __restrict__ Wr0, const float* __restrict__ br0,
    const float* __restrict__ Wr1, const float* __restrict__ br1,
    const float* __restrict__ Wr2, const float* __restrict__ br2,
    const float* __restrict__ Wz0, const float* __restrict__ bz0,
    const float* __restrict__ Wz1, const float* __restrict__ bz1,
    const float* __restrict__ Wz2, const float* __restrict__ bz2,
    const float* __restrict__ Wh0, const float* __restrict__ bh0,
    const float* __restrict__ Wh1, const float* __restrict__ bh1,
    const float* __restrict__ Wh2, const float* __restrict__ bh2,
    float* __restrict__ out)
{
    extern __shared__ __align__(16) float dsm[];
    float* WR1 = dsm;                 // 4 matrices, rows padded to 68 floats
    float* WR2 = WR1 + 4352;
    float* WZ1 = WR2 + 4352;
    float* WH1 = WZ1 + 4352;
    float* GBUF = WH1 + 4352;         // 8 groups x 4 buffers x 16*64
    __shared__ int sIdx[8 * 16];

    int tid = threadIdx.x;
    int g = tid >> 6, o = tid & 63;

    // load 4 weight matrices into padded smem rows
    {
        const float* Wsrc[4] = {Wr1, Wr2, Wz1, Wh1};
        for (int i = tid; i < 4 * 4096; i += 512) {
            int m = i >> 12, r = i & 4095;
            dsm[m * 4352 + (r >> 6) * 68 + (r & 63)] = Wsrc[m][r];
        }
    }

    int q = blockIdx.x * 8 + g;
    int b = q >> 12, n = q & 4095;
    if (o < 16) sIdx[g * 16 + o] = g_idx[q * KSEL + o];

    float wr0x = Wr0[o * 3], wr0y = Wr0[o * 3 + 1], wr0z = Wr0[o * 3 + 2];
    float wz0x = Wz0[o * 3], wz0y = Wz0[o * 3 + 1], wz0z = Wz0[o * 3 + 2];
    float wh0x = Wh0[o * 3], wh0y = Wh0[o * 3 + 1], wh0z = Wh0[o * 3 + 2];
    float br0o = br0[o], br1o = br1[o], br2o = br2[o];
    float bz0o = bz0[o], bz1o = bz1[o];
    float bh0o = bh0[o], bh1o = bh1[o];
    float bz2o = bz2[o], bh2o = bh2[o];
    size_t nb = (size_t)b * N1 + n;
    float gp1ro = g_gp1r[nb * 64 + o];
    float gp1zo = g_gp1z[nb * 64 + o];
    float p1oo  = g_p1o [nb * 64 + o];
    float x1x = xyz1[(b * 3 + 0) * N1 + n];
    float x1y = xyz1[(b * 3 + 1) * N1 + n];
    float x1z = xyz1[(b * 3 + 2) * N1 + n];

    float* T = GBUF + g * 4096;   // t0[k][o]; tail: zmax/hmax vectors
    float* U = T + 1024;          // u0[k][o]
    float* V = U + 1024;          // h partial -> v0[k][o]
    float* S = V + 1024;          // t1[k][o]

    __syncthreads();   // weights + sIdx ready

    // ---- Stage A: elementwise layer-0 for all k ----
    #pragma unroll 2
    for (int k = 0; k < KSEL; k++) {
        int j = sIdx[g * 16 + k];
        size_t gb = ((size_t)b * N2 + j) * 64 + o;
        float gr  = g_p2r [gb];
        float gro = g_p2ro[gb];
        float gz  = g_p2z [gb];
        float dx = __ldg(&xyz2[(b * 3 + 0) * N2 + j]) - x1x;
        float dy = __ldg(&xyz2[(b * 3 + 1) * N2 + j]) - x1y;
        float dz = __ldg(&xyz2[(b * 3 + 2) * N2 + j]) - x1z;
        T[k * 64 + o] = leaky(fmaf(wr0x, dx, fmaf(wr0y, dy, fmaf(wr0z, dz, br0o + gp1ro + gr))));
        U[k * 64 + o] = leaky(fmaf(wz0x, dx, fmaf(wz0y, dy, fmaf(wz0z, dz, bz0o + gp1zo + gro))));
        V[k * 64 + o] = fmaf(wh0x, dx, fmaf(wh0y, dy, fmaf(wh0z, dz, bh0o + gz)));
    }
    GBAR(g);   // (1) T,U,V visible

    ulonglong2 w[16];
    // ---- pass WR1: S[k] = t1[k] (own-element smem writes, no local array) ----
    loadrow(WR1, o, w);
    #pragma unroll 1
    for (int k = 0; k < KSEL; k++)
        S[k * 64 + o] = leaky(dotv64(w, T + k * 64) + br1o);
    // ---- pass WZ1: zmax ----
    loadrow(WZ1, o, w);
    float zmax = -1e30f;
    #pragma unroll 1
    for (int k = 0; k < KSEL; k++)
        zmax = fmaxf(zmax, leaky(dotv64(w, U + k * 64) + bz1o));
    GBAR(g);   // (2) S visible; T,U reads done
    // ---- pass WR2: r[k] from S, update V in place ----
    loadrow(WR2, o, w);
    #pragma unroll 1
    for (int k = 0; k < KSEL; k++) {
        float r = sigm(dotv64(w, S + k * 64) + br2o);
        V[k * 64 + o] = leaky(fmaf(r, p1oo, V[k * 64 + o]));
    }
    GBAR(g);   // (3) V updates visible
    // ---- pass WH1: hmax ----
    loadrow(WH1, o, w);
    float hmax = -1e30f;
    #pragma unroll 1
    for (int k = 0; k < KSEL; k++)
        hmax = fmaxf(hmax, leaky(dotv64(w, V + k * 64) + bh1o));

    T[o] = zmax;
    T[64 + o] = hmax;
    GBAR(g);   // (4) zmax/hmax vectors visible

    // ---- final layer: weights from gmem (L1-hot across groups) ----
    float z = sigm(gdot64(Wz2 + o * 64, T) + bz2o);
    float h = leaky(gdot64(Wh2 + o * 64, T + 64) + bh2o);
    out[((size_t)b * 64 + o) * N1 + n] = (1.f - z) * p1oo + z * h;
}

// ---------------- launch ----------------
extern "C" void kernel_launch(void* const* d_in, const int* in_sizes, int n_in,
                              void* d_out, int out_size) {
    (void)in_sizes; (void)n_in; (void)out_size;
    const float* xyz1    = (const float*)d_in[0];
    const float* xyz2    = (const float*)d_in[1];
    const float* points1 = (const float*)d_in[2];
    const float* points2 = (const float*)d_in[3];
    const float* knn1    = (const float*)d_in[4];
    const float* knn2    = (const float*)d_in[5];
    const float* Wfr   = (const float*)d_in[6];
    const float* Wfro  = (const float*)d_in[7];
    const float* Wfz   = (const float*)d_in[8];
    const float* Wfr2  = (const float*)d_in[9];
    const float* Wfro2 = (const float*)d_in[10];
    const float* Wfz2  = (const float*)d_in[11];
    const float* Wr0 = (const float*)d_in[12]; const float* br0 = (const float*)d_in[13];
    const float* Wr1 = (const float*)d_in[14]; const float* br1 = (const float*)d_in[15];
    const float* Wr2 = (const float*)d_in[16]; const float* br2 = (const float*)d_in[17];
    const float* Wz0 = (const float*)d_in[18]; const float* bz0 = (const float*)d_in[19];
    const float* Wz1 = (const float*)d_in[20]; const float* bz1 = (const float*)d_in[21];
    const float* Wz2 = (const float*)d_in[22]; const float* bz2 = (const float*)d_in[23];
    const float* Wh0 = (const float*)d_in[24]; const float* bh0 = (const float*)d_in[25];
    const float* Wh1 = (const float*)d_in[26]; const float* bh1 = (const float*)d_in[27];
    const float* Wh2 = (const float*)d_in[28]; const float* bh2 = (const float*)d_in[29];
    float* out = (float*)d_out;

    float *f1n, *f2n, *p2r, *p2ro, *p2z, *gp1r, *gp1z, *p1o;
    cudaGetSymbolAddress((void**)&f1n,  g_f1n);
    cudaGetSymbolAddress((void**)&f2n,  g_f2n);
    cudaGetSymbolAddress((void**)&p2r,  g_p2r);
    cudaGetSymbolAddress((void**)&p2ro, g_p2ro);
    cudaGetSymbolAddress((void**)&p2z,  g_p2z);
    cudaGetSymbolAddress((void**)&gp1r, g_gp1r);
    cudaGetSymbolAddress((void**)&gp1z, g_gp1z);
    cudaGetSymbolAddress((void**)&p1o,  g_p1o);

    const int MLP_SMEM = (4 * 4352 + 8 * 4 * 1024) * 4;  // 200704 B
    cudaFuncSetAttribute(k_mlp, cudaFuncAttributeMaxDynamicSharedMemorySize, MLP_SMEM);

    // [0] normalize both knn tensors
    k_norm_both<<<dim3((N1 + N2) / 64, BB), 256>>>(knn1, knn2, f1n, f2n);
    // [1] fused cos+euc knn partials
    k_knn_both<<<dim3(N1 / 128, 16, BB), 128>>>(xyz1, xyz2);
    // [2][3] projections (3 weight variants per launch via blockIdx.z)
    k_project_m<<<dim3(N2 / 64, BB, 3), 256>>>(points2, Wfr2, Wfro2, Wfz2, p2r, p2ro, p2z, N2);
    k_project_m<<<dim3(N1 / 64, BB, 3), 256>>>(points1, Wfr,  Wfz,   Wfro, gp1r, gp1z, p1o, N1);
    // [4] merge partial top-8 lists
    k_merge<<<(BB * N1) / 256, 256>>>();
    // [5] fused GRU MLP  (ncu -s 5 -c 1 captures this launch)
    k_mlp<<<(BB * N1) / 8, 512, MLP_SMEM>>>(
        xyz1, xyz2,
        Wr0, br0, Wr1, br1, Wr2, br2,
        Wz0, bz0, Wz1, bz1, Wz2, bz2,
        Wh0, bh0, Wh1, bh1, Wh2, bh2,
        out);
}